// round 14
// baseline (speedup 1.0000x reference)
#include <cuda_runtime.h>
#include <cuda_fp16.h>
#include <cstdint>

#define Bc   2
#define Tc   2048
#define Cc   2048
#define NH   16
#define NKV  2
#define DH   128
#define Mrows (Bc*Tc)          // 4096
#define QKVW 2560              // q(2048) | k(256) | v(256)

// ---------------- scratch (allocation-free rule: __device__ globals) --------
__device__ __align__(16) __half g_xh  [(size_t)Mrows * Cc];
__device__ __align__(16) __half g_qkv [(size_t)Mrows * QKVW];
__device__ __align__(16) __half g_yh  [(size_t)Mrows * Cc];
__device__ __align__(16) __half g_wqkvt[(size_t)QKVW * Cc];
__device__ __align__(16) __half g_wot [(size_t)Cc * Cc];

__device__ __forceinline__ float ex2(float x) {
    float y; asm("ex2.approx.f32 %0, %1;" : "=f"(y) : "f"(x)); return y;
}
__device__ __forceinline__ uint32_t smem_to_u32(const void* p) {
    uint32_t a;
    asm("{ .reg .u64 t; cvta.to.shared.u64 t, %1; cvt.u32.u64 %0, t; }"
        : "=r"(a) : "l"(p));
    return a;
}
__device__ __forceinline__ uint32_t pack_h2(float lo, float hi) {
    __half2 h = __floats2half2_rn(lo, hi);
    return *(uint32_t*)&h;
}
__device__ __forceinline__ void mma_f16(float* c, const uint32_t* a, const uint32_t* b) {
    asm volatile(
        "mma.sync.aligned.m16n8k16.row.col.f32.f16.f16.f32 "
        "{%0,%1,%2,%3}, {%4,%5,%6,%7}, {%8,%9}, {%0,%1,%2,%3};"
        : "+f"(c[0]), "+f"(c[1]), "+f"(c[2]), "+f"(c[3])
        : "r"(a[0]), "r"(a[1]), "r"(a[2]), "r"(a[3]), "r"(b[0]), "r"(b[1]));
}
#define LDMATRIX_X4(r0, r1, r2, r3, addr) \
    asm volatile("ldmatrix.sync.aligned.m8n8.x4.shared.b16 {%0,%1,%2,%3}, [%4];" \
        : "=r"(r0), "=r"(r1), "=r"(r2), "=r"(r3) : "r"(addr))
#define LDMATRIX_X4_TRANS(r0, r1, r2, r3, addr) \
    asm volatile("ldmatrix.sync.aligned.m8n8.x4.trans.shared.b16 {%0,%1,%2,%3}, [%4];" \
        : "=r"(r0), "=r"(r1), "=r"(r2), "=r"(r3) : "r"(addr))
#define CP_ASYNC16(sm, gp) \
    asm volatile("cp.async.cg.shared.global [%0], [%1], 16;" :: "r"(sm), "l"(gp))
#define CP_COMMIT asm volatile("cp.async.commit_group;" ::: "memory")
#define CP_WAIT1  asm volatile("cp.async.wait_group 1;"  ::: "memory")

// =================== fp16 mma GEMM (round-8 config, known best) =============
// C[M,N] = A[M,K] @ Bt[N,K]^T. CTA 128x128, 4 warps @ 64x64,
// K-chunk 32 halves, 3-stage cp.async, 2 CTAs/SM.
#define KCG 32                          // K-chunk (halves)
#define KPG 40                          // smem row stride (halves)
#define GA_H (128*KPG)                  // halves per A stage
#define STG_H (2*GA_H)                  // A + B
#define GEMM_SMEM (3 * STG_H * 2)       // 61440 B

__global__ __launch_bounds__(128, 2) void gemm_hmma(
    const __half* __restrict__ A, const __half* __restrict__ Bt,
    float* __restrict__ Cf, __half* __restrict__ Ch,
    int M, int N, int K, int out_half)
{
    extern __shared__ __half smg[];
    const uint32_t smb = smem_to_u32(smg);
    const int tid = threadIdx.x, wid = tid >> 5, lane = tid & 31;
    const int lr = lane >> 2, lc = lane & 3;
    const int wm = (wid & 1) * 64;
    const int wn = (wid >> 1) * 64;
    const int bm = blockIdx.y * 128;
    const int bn = blockIdx.x * 128;
    const int nc = K / KCG;

    const int a_row = lane & 15, a_k = (lane >> 4) * 8;
    const int b_row = (lane & 7) + ((lane >> 4) << 3), b_k = lane & 8;

    float acc[4][8][4];
#pragma unroll
    for (int i = 0; i < 4; i++)
#pragma unroll
        for (int j = 0; j < 8; j++)
#pragma unroll
            for (int r = 0; r < 4; r++) acc[i][j][r] = 0.f;

#define GISSUE(chunk) do {                                                      \
        const uint32_t bse = smb + (uint32_t)((chunk) % 3) * (STG_H * 2);       \
        const int kb = (chunk) * KCG;                                           \
        _Pragma("unroll")                                                       \
        for (int n = 0; n < 4; n++) {                                           \
            int i = tid + n * 128, r = i >> 2, cc = (i & 3) * 8;                \
            CP_ASYNC16(bse + (uint32_t)(r * KPG + cc) * 2u,                     \
                       A + (size_t)(bm + r) * K + kb + cc);                     \
            CP_ASYNC16(bse + (uint32_t)(GA_H * 2) + (uint32_t)(r * KPG + cc) * 2u, \
                       Bt + (size_t)(bn + r) * K + kb + cc);                    \
        }                                                                       \
    } while (0)

    GISSUE(0); CP_COMMIT;
    GISSUE(1); CP_COMMIT;

    for (int c = 0; c < nc; c++) {
        CP_WAIT1;
        __syncthreads();
        if (c + 2 < nc) GISSUE(c + 2);
        CP_COMMIT;

        const uint32_t sA = smb + (uint32_t)(c % 3) * (STG_H * 2);
        const uint32_t sB = sA + GA_H * 2;
#pragma unroll
        for (int ks = 0; ks < 2; ks++) {
            const int k0 = ks * 16;
            uint32_t af[4][4], bf[8][2];
#pragma unroll
            for (int mf = 0; mf < 4; mf++) {
                const uint32_t ad = sA +
                    (uint32_t)((wm + mf*16 + a_row) * KPG + k0 + a_k) * 2u;
                LDMATRIX_X4(af[mf][0], af[mf][1], af[mf][2], af[mf][3], ad);
            }
#pragma unroll
            for (int ng = 0; ng < 4; ng++) {
                const uint32_t ad = sB +
                    (uint32_t)((wn + ng*16 + b_row) * KPG + k0 + b_k) * 2u;
                uint32_t r0, r1, r2, r3;
                LDMATRIX_X4(r0, r1, r2, r3, ad);
                bf[2*ng][0] = r0;   bf[2*ng][1] = r1;
                bf[2*ng+1][0] = r2; bf[2*ng+1][1] = r3;
            }
#pragma unroll
            for (int mf = 0; mf < 4; mf++)
#pragma unroll
                for (int nf = 0; nf < 8; nf++)
                    mma_f16(acc[mf][nf], af[mf], bf[nf]);
        }
    }

#pragma unroll
    for (int mf = 0; mf < 4; mf++) {
#pragma unroll
        for (int nf = 0; nf < 8; nf++) {
            const int row = bm + wm + mf * 16 + lr;
            const int col = bn + wn + nf * 8 + lc * 2;
            if (out_half) {
                *(uint32_t*)(Ch + (size_t)row * N + col) =
                    pack_h2(acc[mf][nf][0], acc[mf][nf][1]);
                *(uint32_t*)(Ch + (size_t)(row + 8) * N + col) =
                    pack_h2(acc[mf][nf][2], acc[mf][nf][3]);
            } else {
                *(float2*)(Cf + (size_t)row * N + col) =
                    make_float2(acc[mf][nf][0], acc[mf][nf][1]);
                *(float2*)(Cf + (size_t)(row + 8) * N + col) =
                    make_float2(acc[mf][nf][2], acc[mf][nf][3]);
            }
        }
    }
#undef GISSUE
}

// =================== fused prep kernel ======================================
#define PREP_GRID 11264

__global__ __launch_bounds__(256) void prep(
    const float* __restrict__ x,
    const float* __restrict__ Wq, const float* __restrict__ Wk,
    const float* __restrict__ Wv, const float* __restrict__ Wo)
{
    const int bid = blockIdx.x, tid = threadIdx.x;
    if (bid < 9216) {
        __shared__ float t[32][33];
        const float* in; __half* out; int K, N, bx, by;
        if (bid < 4096)      { in = Wq; out = g_wqkvt;                     K = Cc; N = Cc;  bx = bid & 63;        by = bid >> 6; }
        else if (bid < 4608) { in = Wk; out = g_wqkvt + (size_t)2048 * Cc; K = Cc; N = 256; bx = (bid-4096) & 7;  by = (bid-4096) >> 3; }
        else if (bid < 5120) { in = Wv; out = g_wqkvt + (size_t)2304 * Cc; K = Cc; N = 256; bx = (bid-4608) & 7;  by = (bid-4608) >> 3; }
        else                 { in = Wo; out = g_wot;                       K = Cc; N = Cc;  bx = (bid-5120) & 63; by = (bid-5120) >> 6; }
        const int xx = tid & 31, yy = tid >> 5;
        const int n0 = bx * 32, k0 = by * 32;
        for (int i = yy; i < 32; i += 8)
            t[i][xx] = in[(size_t)(k0 + i) * N + n0 + xx];
        __syncthreads();
        for (int i = yy; i < 32; i += 8)
            out[(size_t)(n0 + i) * K + k0 + xx] = __float2half_rn(t[xx][i]);
    } else {
        const int n4 = Mrows * Cc / 4;
        const float4* in = (const float4*)x;
        __half2* out = (__half2*)g_xh;
        for (int i = (bid - 9216) * 256 + tid; i < n4; i += 2048 * 256) {
            float4 v = in[i];
            out[2*i]   = __floats2half2_rn(v.x, v.y);
            out[2*i+1] = __floats2half2_rn(v.z, v.w);
        }
    }
}

// =================== fp16 mma flash attention ===============================
// BQ=64 (4 warps x 16 rows), BK=128, 128 threads, 2 CTAs/SM.
// 3-buffer smem: K double-buffered, V single-buffered (issued one iter ahead).
// Diagonal block: warp-uniform trimming of fully-masked 16-key groups.
#define BQ 64
#define BK 128
#define KPH 136
#define KTILE (BK * KPH * 2)              // 34816 B
#define ATT_SMEM (3 * KTILE)              // 104448 B -> 2 CTAs/SM

__global__ __launch_bounds__(128, 2) void attn_hmma()
{
    extern __shared__ __half smh[];
    const uint32_t smb = smem_to_u32(smh);
    const int tid = threadIdx.x, wid = tid >> 5, lane = tid & 31;
    const int lr = lane >> 2, lc = lane & 3;
    const int qt = (int)(gridDim.x - 1 - blockIdx.x);   // heavy tiles first
    const int h = blockIdx.y, b = blockIdx.z, g = h >> 3;
    const int q0 = qt * BQ, m0 = wid * 16;

    const uint32_t offK0 = 0, offK1 = KTILE, offV = 2*KTILE;

    const int b_row = (lane & 7) + ((lane >> 4) << 3), b_k = lane & 8;

    uint32_t qf[8][4];
    {
        const __half* q0p = g_qkv + ((size_t)(b*Tc + q0 + m0 + lr))*QKVW + h*DH;
        const __half* q8p = q0p + (size_t)8*QKVW;
#pragma unroll
        for (int ks = 0; ks < 8; ks++) {
            qf[ks][0] = *(const uint32_t*)(q0p + ks*16 + 2*lc);
            qf[ks][1] = *(const uint32_t*)(q8p + ks*16 + 2*lc);
            qf[ks][2] = *(const uint32_t*)(q0p + ks*16 + 2*lc + 8);
            qf[ks][3] = *(const uint32_t*)(q8p + ks*16 + 2*lc + 8);
        }
    }

    float of[16][4];
#pragma unroll
    for (int i = 0; i < 16; i++)
#pragma unroll
        for (int r = 0; r < 4; r++) of[i][r] = 0.f;
    float mrow0 = -1e30f, mrow1 = -1e30f, lrow0 = 0.f, lrow1 = 0.f;
    const float cs = 0.12752191711633058f;   // log2(e)/sqrt(128)

    const __half* gK = g_qkv + (size_t)(b*Tc)*QKVW + 2048 + g*DH;
    const __half* gV = gK + 256;
    const int nb = qt / 2 + 1;     // #128-key blocks covering keys <= q0+63

#define AFILL(dst, src) do {                                                  \
        _Pragma("unroll")                                                     \
        for (int n = 0; n < 16; n++) {                                        \
            int i = tid + n*128;                                              \
            int r = i >> 4, c = (i & 15) * 8;                                 \
            CP_ASYNC16((dst) + (uint32_t)(r*KPH + c)*2u,                      \
                       (src) + (size_t)r*QKVW + c);                           \
        }                                                                     \
    } while (0)

    // prologue: K0, V0, K1 (empty-commit if absent)
    AFILL(smb + offK0, gK); CP_COMMIT;
    AFILL(smb + offV,  gV); CP_COMMIT;
    if (nb > 1) AFILL(smb + offK1, gK + (size_t)BK*QKVW);
    CP_COMMIT;

    for (int jt = 0; jt < nb; jt++) {
        CP_WAIT1;              // K_jt and V_jt landed; K_{jt+1} may fly
        __syncthreads();

        const uint32_t Kb = smb + ((jt & 1) ? offK1 : offK0);
        const uint32_t Vb = smb + offV;
        const int k0 = jt * BK;

        // warp-uniform limit on 16-key groups (diagonal block only):
        // group ng needed iff k0 + ng*16 <= q0 + m0 + 15.
        const int nglim = (jt == nb - 1) ? ((q0 - k0 + m0 + 15) >> 4) + 1 : 8;

        // ---- S = Q @ K^T (16 x 128 per warp, trimmed on diagonal)
        float sf[16][4];
#pragma unroll
        for (int nf = 0; nf < 16; nf++)
#pragma unroll
            for (int r = 0; r < 4; r++) sf[nf][r] = 0.f;

#pragma unroll
        for (int ks = 0; ks < 8; ks++) {
            uint32_t bf[16][2];
#pragma unroll
            for (int ng = 0; ng < 8; ng++) {
                if (ng < nglim) {
                    const uint32_t ad = Kb +
                        (uint32_t)((ng*16 + b_row) * KPH + ks*16 + b_k) * 2u;
                    uint32_t r0, r1, r2, r3;
                    LDMATRIX_X4(r0, r1, r2, r3, ad);
                    bf[2*ng][0] = r0;   bf[2*ng][1] = r1;
                    bf[2*ng+1][0] = r2; bf[2*ng+1][1] = r3;
                }
            }
#pragma unroll
            for (int nf = 0; nf < 16; nf++)
                if ((nf >> 1) < nglim)
                    mma_f16(sf[nf], qf[ks], bf[nf]);
        }

#pragma unroll
        for (int nf = 0; nf < 16; nf++) {
            sf[nf][0] *= cs; sf[nf][1] *= cs; sf[nf][2] *= cs; sf[nf][3] *= cs;
        }
        if (jt == nb - 1) {    // mask full range: covers skipped groups too
            const int row0 = q0 + m0 + lr, row1 = row0 + 8;
#pragma unroll
            for (int nf = 0; nf < 16; nf++) {
                const int col = k0 + nf*8 + lc*2;
                if (col     > row0) sf[nf][0] = -1e30f;
                if (col + 1 > row0) sf[nf][1] = -1e30f;
                if (col     > row1) sf[nf][2] = -1e30f;
                if (col + 1 > row1) sf[nf][3] = -1e30f;
            }
        }

        // ---- online softmax (log2 domain)
        float mx0 = mrow0, mx1 = mrow1;
#pragma unroll
        for (int nf = 0; nf < 16; nf++) {
            mx0 = fmaxf(mx0, fmaxf(sf[nf][0], sf[nf][1]));
            mx1 = fmaxf(mx1, fmaxf(sf[nf][2], sf[nf][3]));
        }
        mx0 = fmaxf(mx0, __shfl_xor_sync(0xffffffffu, mx0, 1, 4));
        mx0 = fmaxf(mx0, __shfl_xor_sync(0xffffffffu, mx0, 2, 4));
        mx1 = fmaxf(mx1, __shfl_xor_sync(0xffffffffu, mx1, 1, 4));
        mx1 = fmaxf(mx1, __shfl_xor_sync(0xffffffffu, mx1, 2, 4));
        const float alpha0 = ex2(mrow0 - mx0);
        const float alpha1 = ex2(mrow1 - mx1);
        mrow0 = mx0; mrow1 = mx1;

        float s0 = 0.f, s1 = 0.f;
#pragma unroll
        for (int nf = 0; nf < 16; nf++) {
            sf[nf][0] = ex2(sf[nf][0] - mx0);
            sf[nf][1] = ex2(sf[nf][1] - mx0);
            sf[nf][2] = ex2(sf[nf][2] - mx1);
            sf[nf][3] = ex2(sf[nf][3] - mx1);
            s0 += sf[nf][0] + sf[nf][1];
            s1 += sf[nf][2] + sf[nf][3];
        }
        s0 += __shfl_xor_sync(0xffffffffu, s0, 1, 4);
        s0 += __shfl_xor_sync(0xffffffffu, s0, 2, 4);
        s1 += __shfl_xor_sync(0xffffffffu, s1, 1, 4);
        s1 += __shfl_xor_sync(0xffffffffu, s1, 2, 4);
        lrow0 = lrow0 * alpha0 + s0;
        lrow1 = lrow1 * alpha1 + s1;

#pragma unroll
        for (int nf2 = 0; nf2 < 16; nf2++) {
            of[nf2][0] *= alpha0; of[nf2][1] *= alpha0;
            of[nf2][2] *= alpha1; of[nf2][3] *= alpha1;
        }

        // ---- O += P @ V (P in-register, V via ldmatrix.trans; trimmed)
#pragma unroll
        for (int ks2 = 0; ks2 < 8; ks2++) {
            if (ks2 < nglim) {   // P for keys beyond nglim*16 is exactly 0
                uint32_t pf[4];
                pf[0] = pack_h2(sf[2*ks2][0],   sf[2*ks2][1]);
                pf[1] = pack_h2(sf[2*ks2][2],   sf[2*ks2][3]);
                pf[2] = pack_h2(sf[2*ks2+1][0], sf[2*ks2+1][1]);
                pf[3] = pack_h2(sf[2*ks2+1][2], sf[2*ks2+1][3]);
                const uint32_t vrow = (uint32_t)(ks2*16 + (lane & 15));
#pragma unroll
                for (int np = 0; np < 8; np++) {
                    const uint32_t vaddr = Vb +
                        (vrow * KPH + (uint32_t)(np*16 + (lane >> 4) * 8)) * 2u;
                    uint32_t v0, v1, v2, v3;
                    LDMATRIX_X4_TRANS(v0, v1, v2, v3, vaddr);
                    uint32_t vf0[2] = {v0, v1}, vf1[2] = {v2, v3};
                    mma_f16(of[2*np],   pf, vf0);
                    mma_f16(of[2*np+1], pf, vf1);
                }
            }
        }
        __syncthreads();   // PV done -> V buffer may be overwritten

        // issue next-iteration V (and K two ahead)
        if (jt + 1 < nb) {
            AFILL(smb + offV, gV + (size_t)(jt+1)*BK*QKVW); CP_COMMIT;
            if (jt + 2 < nb)
                AFILL(smb + (((jt+2) & 1) ? offK1 : offK0),
                      gK + (size_t)(jt+2)*BK*QKVW);
            CP_COMMIT;
        }
    }
#undef AFILL

    const float inv0 = 1.f / lrow0, inv1 = 1.f / lrow1;
    const int row0 = q0 + m0 + lr, row1 = row0 + 8;
#pragma unroll
    for (int nf2 = 0; nf2 < 16; nf2++) {
        const int col = h*DH + nf2*8 + lc*2;
        *(uint32_t*)(g_yh + (size_t)(b*Tc + row0)*Cc + col) =
            pack_h2(of[nf2][0]*inv0, of[nf2][1]*inv0);
        *(uint32_t*)(g_yh + (size_t)(b*Tc + row1)*Cc + col) =
            pack_h2(of[nf2][2]*inv1, of[nf2][3]*inv1);
    }
}

// =================== host side ==============================================
extern "C" void kernel_launch(void* const* d_in, const int* in_sizes, int n_in,
                              void* d_out, int out_size)
{
    const float* x  = (const float*)d_in[0];
    const float* Wq = (const float*)d_in[1];
    const float* Wk = (const float*)d_in[2];
    const float* Wv = (const float*)d_in[3];
    const float* Wo = (const float*)d_in[4];
    float* out = (float*)d_out;

    static bool inited = false;
    static __half *xh, *qkvp, *yh, *wqkvt, *wot;
    if (!inited) {
        cudaGetSymbolAddress((void**)&xh,    g_xh);
        cudaGetSymbolAddress((void**)&qkvp,  g_qkv);
        cudaGetSymbolAddress((void**)&yh,    g_yh);
        cudaGetSymbolAddress((void**)&wqkvt, g_wqkvt);
        cudaGetSymbolAddress((void**)&wot,   g_wot);
        cudaFuncSetAttribute(attn_hmma, cudaFuncAttributeMaxDynamicSharedMemorySize,
                             ATT_SMEM);
        cudaFuncSetAttribute(gemm_hmma, cudaFuncAttributeMaxDynamicSharedMemorySize,
                             GEMM_SMEM);
        inited = true;
    }

    prep<<<PREP_GRID, 256>>>(x, Wq, Wk, Wv, Wo);

    gemm_hmma<<<dim3(QKVW / 128, Mrows / 128), 128, GEMM_SMEM>>>(
        xh, wqkvt, nullptr, qkvp, Mrows, QKVW, Cc, 1);
    attn_hmma<<<dim3(Tc / BQ, NH, Bc), 128, ATT_SMEM>>>();
    gemm_hmma<<<dim3(Cc / 128, Mrows / 128), 128, GEMM_SMEM>>>(
        yh, wot, out, nullptr, Mrows, Cc, Cc, 0);
}

// round 15
// speedup vs baseline: 1.2690x; 1.2690x over previous
#include <cuda_runtime.h>
#include <cuda_fp16.h>
#include <cstdint>

#define Bc   2
#define Tc   2048
#define Cc   2048
#define NH   16
#define NKV  2
#define DH   128
#define Mrows (Bc*Tc)          // 4096
#define QKVW 2560              // q(2048) | k(256) | v(256)

// ---------------- scratch (allocation-free rule: __device__ globals) --------
__device__ __align__(16) __half g_xh  [(size_t)Mrows * Cc];
__device__ __align__(16) __half g_qkv [(size_t)Mrows * QKVW];
__device__ __align__(16) __half g_yh  [(size_t)Mrows * Cc];
__device__ __align__(16) __half g_wqkvt[(size_t)QKVW * Cc];
__device__ __align__(16) __half g_wot [(size_t)Cc * Cc];

__device__ __forceinline__ float ex2(float x) {
    float y; asm("ex2.approx.f32 %0, %1;" : "=f"(y) : "f"(x)); return y;
}
__device__ __forceinline__ uint32_t smem_to_u32(const void* p) {
    uint32_t a;
    asm("{ .reg .u64 t; cvta.to.shared.u64 t, %1; cvt.u32.u64 %0, t; }"
        : "=r"(a) : "l"(p));
    return a;
}
__device__ __forceinline__ uint32_t pack_h2(float lo, float hi) {
    __half2 h = __floats2half2_rn(lo, hi);
    return *(uint32_t*)&h;
}
__device__ __forceinline__ void mma_f16(float* c, const uint32_t* a, const uint32_t* b) {
    asm volatile(
        "mma.sync.aligned.m16n8k16.row.col.f32.f16.f16.f32 "
        "{%0,%1,%2,%3}, {%4,%5,%6,%7}, {%8,%9}, {%0,%1,%2,%3};"
        : "+f"(c[0]), "+f"(c[1]), "+f"(c[2]), "+f"(c[3])
        : "r"(a[0]), "r"(a[1]), "r"(a[2]), "r"(a[3]), "r"(b[0]), "r"(b[1]));
}
#define LDMATRIX_X4(r0, r1, r2, r3, addr) \
    asm volatile("ldmatrix.sync.aligned.m8n8.x4.shared.b16 {%0,%1,%2,%3}, [%4];" \
        : "=r"(r0), "=r"(r1), "=r"(r2), "=r"(r3) : "r"(addr))
#define LDMATRIX_X4_TRANS(r0, r1, r2, r3, addr) \
    asm volatile("ldmatrix.sync.aligned.m8n8.x4.trans.shared.b16 {%0,%1,%2,%3}, [%4];" \
        : "=r"(r0), "=r"(r1), "=r"(r2), "=r"(r3) : "r"(addr))
#define CP_ASYNC16(sm, gp) \
    asm volatile("cp.async.cg.shared.global [%0], [%1], 16;" :: "r"(sm), "l"(gp))
#define CP_COMMIT asm volatile("cp.async.commit_group;" ::: "memory")
#define CP_WAIT1  asm volatile("cp.async.wait_group 1;"  ::: "memory")

// =================== fp16 mma GEMM (round-8 config, known best) =============
// C[M,N] = A[M,K] @ Bt[N,K]^T. CTA 128x128, 4 warps @ 64x64,
// K-chunk 32 halves, 3-stage cp.async, 2 CTAs/SM.
#define KCG 32                          // K-chunk (halves)
#define KPG 40                          // smem row stride (halves)
#define GA_H (128*KPG)                  // halves per A stage
#define STG_H (2*GA_H)                  // A + B
#define GEMM_SMEM (3 * STG_H * 2)       // 61440 B

__global__ __launch_bounds__(128, 2) void gemm_hmma(
    const __half* __restrict__ A, const __half* __restrict__ Bt,
    float* __restrict__ Cf, __half* __restrict__ Ch,
    int M, int N, int K, int out_half)
{
    extern __shared__ __half smg[];
    const uint32_t smb = smem_to_u32(smg);
    const int tid = threadIdx.x, wid = tid >> 5, lane = tid & 31;
    const int lr = lane >> 2, lc = lane & 3;
    const int wm = (wid & 1) * 64;
    const int wn = (wid >> 1) * 64;
    const int bm = blockIdx.y * 128;
    const int bn = blockIdx.x * 128;
    const int nc = K / KCG;

    const int a_row = lane & 15, a_k = (lane >> 4) * 8;
    const int b_row = (lane & 7) + ((lane >> 4) << 3), b_k = lane & 8;

    float acc[4][8][4];
#pragma unroll
    for (int i = 0; i < 4; i++)
#pragma unroll
        for (int j = 0; j < 8; j++)
#pragma unroll
            for (int r = 0; r < 4; r++) acc[i][j][r] = 0.f;

#define GISSUE(chunk) do {                                                      \
        const uint32_t bse = smb + (uint32_t)((chunk) % 3) * (STG_H * 2);       \
        const int kb = (chunk) * KCG;                                           \
        _Pragma("unroll")                                                       \
        for (int n = 0; n < 4; n++) {                                           \
            int i = tid + n * 128, r = i >> 2, cc = (i & 3) * 8;                \
            CP_ASYNC16(bse + (uint32_t)(r * KPG + cc) * 2u,                     \
                       A + (size_t)(bm + r) * K + kb + cc);                     \
            CP_ASYNC16(bse + (uint32_t)(GA_H * 2) + (uint32_t)(r * KPG + cc) * 2u, \
                       Bt + (size_t)(bn + r) * K + kb + cc);                    \
        }                                                                       \
    } while (0)

    GISSUE(0); CP_COMMIT;
    GISSUE(1); CP_COMMIT;

    for (int c = 0; c < nc; c++) {
        CP_WAIT1;
        __syncthreads();
        if (c + 2 < nc) GISSUE(c + 2);
        CP_COMMIT;

        const uint32_t sA = smb + (uint32_t)(c % 3) * (STG_H * 2);
        const uint32_t sB = sA + GA_H * 2;
#pragma unroll
        for (int ks = 0; ks < 2; ks++) {
            const int k0 = ks * 16;
            uint32_t af[4][4], bf[8][2];
#pragma unroll
            for (int mf = 0; mf < 4; mf++) {
                const uint32_t ad = sA +
                    (uint32_t)((wm + mf*16 + a_row) * KPG + k0 + a_k) * 2u;
                LDMATRIX_X4(af[mf][0], af[mf][1], af[mf][2], af[mf][3], ad);
            }
#pragma unroll
            for (int ng = 0; ng < 4; ng++) {
                const uint32_t ad = sB +
                    (uint32_t)((wn + ng*16 + b_row) * KPG + k0 + b_k) * 2u;
                uint32_t r0, r1, r2, r3;
                LDMATRIX_X4(r0, r1, r2, r3, ad);
                bf[2*ng][0] = r0;   bf[2*ng][1] = r1;
                bf[2*ng+1][0] = r2; bf[2*ng+1][1] = r3;
            }
#pragma unroll
            for (int mf = 0; mf < 4; mf++)
#pragma unroll
                for (int nf = 0; nf < 8; nf++)
                    mma_f16(acc[mf][nf], af[mf], bf[nf]);
        }
    }

#pragma unroll
    for (int mf = 0; mf < 4; mf++) {
#pragma unroll
        for (int nf = 0; nf < 8; nf++) {
            const int row = bm + wm + mf * 16 + lr;
            const int col = bn + wn + nf * 8 + lc * 2;
            if (out_half) {
                *(uint32_t*)(Ch + (size_t)row * N + col) =
                    pack_h2(acc[mf][nf][0], acc[mf][nf][1]);
                *(uint32_t*)(Ch + (size_t)(row + 8) * N + col) =
                    pack_h2(acc[mf][nf][2], acc[mf][nf][3]);
            } else {
                *(float2*)(Cf + (size_t)row * N + col) =
                    make_float2(acc[mf][nf][0], acc[mf][nf][1]);
                *(float2*)(Cf + (size_t)(row + 8) * N + col) =
                    make_float2(acc[mf][nf][2], acc[mf][nf][3]);
            }
        }
    }
#undef GISSUE
}

// =================== fused prep kernel ======================================
#define PREP_GRID 11264

__global__ __launch_bounds__(256) void prep(
    const float* __restrict__ x,
    const float* __restrict__ Wq, const float* __restrict__ Wk,
    const float* __restrict__ Wv, const float* __restrict__ Wo)
{
    const int bid = blockIdx.x, tid = threadIdx.x;
    if (bid < 9216) {
        __shared__ float t[32][33];
        const float* in; __half* out; int K, N, bx, by;
        if (bid < 4096)      { in = Wq; out = g_wqkvt;                     K = Cc; N = Cc;  bx = bid & 63;        by = bid >> 6; }
        else if (bid < 4608) { in = Wk; out = g_wqkvt + (size_t)2048 * Cc; K = Cc; N = 256; bx = (bid-4096) & 7;  by = (bid-4096) >> 3; }
        else if (bid < 5120) { in = Wv; out = g_wqkvt + (size_t)2304 * Cc; K = Cc; N = 256; bx = (bid-4608) & 7;  by = (bid-4608) >> 3; }
        else                 { in = Wo; out = g_wot;                       K = Cc; N = Cc;  bx = (bid-5120) & 63; by = (bid-5120) >> 6; }
        const int xx = tid & 31, yy = tid >> 5;
        const int n0 = bx * 32, k0 = by * 32;
        for (int i = yy; i < 32; i += 8)
            t[i][xx] = in[(size_t)(k0 + i) * N + n0 + xx];
        __syncthreads();
        for (int i = yy; i < 32; i += 8)
            out[(size_t)(n0 + i) * K + k0 + xx] = __float2half_rn(t[xx][i]);
    } else {
        const int n4 = Mrows * Cc / 4;
        const float4* in = (const float4*)x;
        __half2* out = (__half2*)g_xh;
        for (int i = (bid - 9216) * 256 + tid; i < n4; i += 2048 * 256) {
            float4 v = in[i];
            out[2*i]   = __floats2half2_rn(v.x, v.y);
            out[2*i+1] = __floats2half2_rn(v.z, v.w);
        }
    }
}

// =================== fp16 mma flash attention ===============================
// BQ=64 (4 warps x 16 rows), BK=128, 128 threads, 2 CTAs/SM.
// 3-buffer smem: K double-buffered, V single-buffered (issued one iter ahead).
// grid (NH*Bc, Tc/BQ): globally heavy-first (y=0 -> heaviest qt).
#define BQ 64
#define BK 128
#define KPH 136
#define KTILE (BK * KPH * 2)              // 34816 B
#define ATT_SMEM (3 * KTILE)              // 104448 B -> 2 CTAs/SM

__global__ __launch_bounds__(128, 2) void attn_hmma()
{
    extern __shared__ __half smh[];
    const uint32_t smb = smem_to_u32(smh);
    const int tid = threadIdx.x, wid = tid >> 5, lane = tid & 31;
    const int lr = lane >> 2, lc = lane & 3;
    const int qt = (int)(gridDim.y - 1 - blockIdx.y);   // globally heavy-first
    const int h = blockIdx.x & (NH - 1), b = blockIdx.x >> 4, g = h >> 3;
    const int q0 = qt * BQ, m0 = wid * 16;

    const uint32_t offK0 = 0, offK1 = KTILE, offV = 2*KTILE;

    const int b_row = (lane & 7) + ((lane >> 4) << 3), b_k = lane & 8;

    uint32_t qf[8][4];
    {
        const __half* q0p = g_qkv + ((size_t)(b*Tc + q0 + m0 + lr))*QKVW + h*DH;
        const __half* q8p = q0p + (size_t)8*QKVW;
#pragma unroll
        for (int ks = 0; ks < 8; ks++) {
            qf[ks][0] = *(const uint32_t*)(q0p + ks*16 + 2*lc);
            qf[ks][1] = *(const uint32_t*)(q8p + ks*16 + 2*lc);
            qf[ks][2] = *(const uint32_t*)(q0p + ks*16 + 2*lc + 8);
            qf[ks][3] = *(const uint32_t*)(q8p + ks*16 + 2*lc + 8);
        }
    }

    float of[16][4];
#pragma unroll
    for (int i = 0; i < 16; i++)
#pragma unroll
        for (int r = 0; r < 4; r++) of[i][r] = 0.f;
    float mrow0 = -1e30f, mrow1 = -1e30f, lrow0 = 0.f, lrow1 = 0.f;
    const float cs = 0.12752191711633058f;   // log2(e)/sqrt(128)

    const __half* gK = g_qkv + (size_t)(b*Tc)*QKVW + 2048 + g*DH;
    const __half* gV = gK + 256;
    const int nb = qt / 2 + 1;     // #128-key blocks covering keys <= q0+63

#define AFILL(dst, src) do {                                                  \
        _Pragma("unroll")                                                     \
        for (int n = 0; n < 16; n++) {                                        \
            int i = tid + n*128;                                              \
            int r = i >> 4, c = (i & 15) * 8;                                 \
            CP_ASYNC16((dst) + (uint32_t)(r*KPH + c)*2u,                      \
                       (src) + (size_t)r*QKVW + c);                           \
        }                                                                     \
    } while (0)

    // prologue: K0, V0, K1 (empty-commit if absent)
    AFILL(smb + offK0, gK); CP_COMMIT;
    AFILL(smb + offV,  gV); CP_COMMIT;
    if (nb > 1) AFILL(smb + offK1, gK + (size_t)BK*QKVW);
    CP_COMMIT;

    for (int jt = 0; jt < nb; jt++) {
        CP_WAIT1;              // K_jt and V_jt landed; K_{jt+1} may fly
        __syncthreads();

        const uint32_t Kb = smb + ((jt & 1) ? offK1 : offK0);
        const uint32_t Vb = smb + offV;
        const int k0 = jt * BK;

        // ---- S = Q @ K^T (16 x 128 per warp)
        float sf[16][4];
#pragma unroll
        for (int nf = 0; nf < 16; nf++)
#pragma unroll
            for (int r = 0; r < 4; r++) sf[nf][r] = 0.f;

#pragma unroll
        for (int ks = 0; ks < 8; ks++) {
            uint32_t bf[16][2];
#pragma unroll
            for (int ng = 0; ng < 8; ng++) {
                const uint32_t ad = Kb +
                    (uint32_t)((ng*16 + b_row) * KPH + ks*16 + b_k) * 2u;
                uint32_t r0, r1, r2, r3;
                LDMATRIX_X4(r0, r1, r2, r3, ad);
                bf[2*ng][0] = r0;   bf[2*ng][1] = r1;
                bf[2*ng+1][0] = r2; bf[2*ng+1][1] = r3;
            }
#pragma unroll
            for (int nf = 0; nf < 16; nf++)
                mma_f16(sf[nf], qf[ks], bf[nf]);
        }

#pragma unroll
        for (int nf = 0; nf < 16; nf++) {
            sf[nf][0] *= cs; sf[nf][1] *= cs; sf[nf][2] *= cs; sf[nf][3] *= cs;
        }
        if (jt == nb - 1) {    // only last block can cross the diagonal
            const int row0 = q0 + m0 + lr, row1 = row0 + 8;
#pragma unroll
            for (int nf = 0; nf < 16; nf++) {
                const int col = k0 + nf*8 + lc*2;
                if (col     > row0) sf[nf][0] = -1e30f;
                if (col + 1 > row0) sf[nf][1] = -1e30f;
                if (col     > row1) sf[nf][2] = -1e30f;
                if (col + 1 > row1) sf[nf][3] = -1e30f;
            }
        }

        // ---- online softmax (log2 domain)
        float mx0 = mrow0, mx1 = mrow1;
#pragma unroll
        for (int nf = 0; nf < 16; nf++) {
            mx0 = fmaxf(mx0, fmaxf(sf[nf][0], sf[nf][1]));
            mx1 = fmaxf(mx1, fmaxf(sf[nf][2], sf[nf][3]));
        }
        mx0 = fmaxf(mx0, __shfl_xor_sync(0xffffffffu, mx0, 1, 4));
        mx0 = fmaxf(mx0, __shfl_xor_sync(0xffffffffu, mx0, 2, 4));
        mx1 = fmaxf(mx1, __shfl_xor_sync(0xffffffffu, mx1, 1, 4));
        mx1 = fmaxf(mx1, __shfl_xor_sync(0xffffffffu, mx1, 2, 4));
        const float alpha0 = ex2(mrow0 - mx0);
        const float alpha1 = ex2(mrow1 - mx1);
        mrow0 = mx0; mrow1 = mx1;

        float s0 = 0.f, s1 = 0.f;
#pragma unroll
        for (int nf = 0; nf < 16; nf++) {
            sf[nf][0] = ex2(sf[nf][0] - mx0);
            sf[nf][1] = ex2(sf[nf][1] - mx0);
            sf[nf][2] = ex2(sf[nf][2] - mx1);
            sf[nf][3] = ex2(sf[nf][3] - mx1);
            s0 += sf[nf][0] + sf[nf][1];
            s1 += sf[nf][2] + sf[nf][3];
        }
        s0 += __shfl_xor_sync(0xffffffffu, s0, 1, 4);
        s0 += __shfl_xor_sync(0xffffffffu, s0, 2, 4);
        s1 += __shfl_xor_sync(0xffffffffu, s1, 1, 4);
        s1 += __shfl_xor_sync(0xffffffffu, s1, 2, 4);
        lrow0 = lrow0 * alpha0 + s0;
        lrow1 = lrow1 * alpha1 + s1;

#pragma unroll
        for (int nf2 = 0; nf2 < 16; nf2++) {
            of[nf2][0] *= alpha0; of[nf2][1] *= alpha0;
            of[nf2][2] *= alpha1; of[nf2][3] *= alpha1;
        }

        // ---- O += P @ V (P in-register, V via ldmatrix.trans)
#pragma unroll
        for (int ks2 = 0; ks2 < 8; ks2++) {
            uint32_t pf[4];
            pf[0] = pack_h2(sf[2*ks2][0],   sf[2*ks2][1]);
            pf[1] = pack_h2(sf[2*ks2][2],   sf[2*ks2][3]);
            pf[2] = pack_h2(sf[2*ks2+1][0], sf[2*ks2+1][1]);
            pf[3] = pack_h2(sf[2*ks2+1][2], sf[2*ks2+1][3]);
            const uint32_t vrow = (uint32_t)(ks2*16 + (lane & 15));
#pragma unroll
            for (int np = 0; np < 8; np++) {
                const uint32_t vaddr = Vb +
                    (vrow * KPH + (uint32_t)(np*16 + (lane >> 4) * 8)) * 2u;
                uint32_t v0, v1, v2, v3;
                LDMATRIX_X4_TRANS(v0, v1, v2, v3, vaddr);
                uint32_t vf0[2] = {v0, v1}, vf1[2] = {v2, v3};
                mma_f16(of[2*np],   pf, vf0);
                mma_f16(of[2*np+1], pf, vf1);
            }
        }
        __syncthreads();   // PV done -> V buffer may be overwritten

        // issue next-iteration V (and K two ahead)
        if (jt + 1 < nb) {
            AFILL(smb + offV, gV + (size_t)(jt+1)*BK*QKVW); CP_COMMIT;
            if (jt + 2 < nb)
                AFILL(smb + (((jt+2) & 1) ? offK1 : offK0),
                      gK + (size_t)(jt+2)*BK*QKVW);
            CP_COMMIT;
        }
    }
#undef AFILL

    const float inv0 = 1.f / lrow0, inv1 = 1.f / lrow1;
    const int row0 = q0 + m0 + lr, row1 = row0 + 8;
#pragma unroll
    for (int nf2 = 0; nf2 < 16; nf2++) {
        const int col = h*DH + nf2*8 + lc*2;
        *(uint32_t*)(g_yh + (size_t)(b*Tc + row0)*Cc + col) =
            pack_h2(of[nf2][0]*inv0, of[nf2][1]*inv0);
        *(uint32_t*)(g_yh + (size_t)(b*Tc + row1)*Cc + col) =
            pack_h2(of[nf2][2]*inv1, of[nf2][3]*inv1);
    }
}

// =================== host side ==============================================
extern "C" void kernel_launch(void* const* d_in, const int* in_sizes, int n_in,
                              void* d_out, int out_size)
{
    const float* x  = (const float*)d_in[0];
    const float* Wq = (const float*)d_in[1];
    const float* Wk = (const float*)d_in[2];
    const float* Wv = (const float*)d_in[3];
    const float* Wo = (const float*)d_in[4];
    float* out = (float*)d_out;

    static bool inited = false;
    static __half *xh, *qkvp, *yh, *wqkvt, *wot;
    if (!inited) {
        cudaGetSymbolAddress((void**)&xh,    g_xh);
        cudaGetSymbolAddress((void**)&qkvp,  g_qkv);
        cudaGetSymbolAddress((void**)&yh,    g_yh);
        cudaGetSymbolAddress((void**)&wqkvt, g_wqkvt);
        cudaGetSymbolAddress((void**)&wot,   g_wot);
        cudaFuncSetAttribute(attn_hmma, cudaFuncAttributeMaxDynamicSharedMemorySize,
                             ATT_SMEM);
        cudaFuncSetAttribute(gemm_hmma, cudaFuncAttributeMaxDynamicSharedMemorySize,
                             GEMM_SMEM);
        inited = true;
    }

    prep<<<PREP_GRID, 256>>>(x, Wq, Wk, Wv, Wo);

    gemm_hmma<<<dim3(QKVW / 128, Mrows / 128), 128, GEMM_SMEM>>>(
        xh, wqkvt, nullptr, qkvp, Mrows, QKVW, Cc, 1);
    attn_hmma<<<dim3(NH * Bc, Tc / BQ), 128, ATT_SMEM>>>();
    gemm_hmma<<<dim3(Cc / 128, Mrows / 128), 128, GEMM_SMEM>>>(
        yh, wot, out, nullptr, Mrows, Cc, Cc, 0);
}

// round 16
// speedup vs baseline: 1.2921x; 1.0182x over previous
#include <cuda_runtime.h>
#include <cuda_fp16.h>
#include <cstdint>

#define Bc   2
#define Tc   2048
#define Cc   2048
#define NH   16
#define NKV  2
#define DH   128
#define Mrows (Bc*Tc)          // 4096
#define QKVW 2560              // q(2048) | k(256) | v(256)

// ---------------- scratch (allocation-free rule: __device__ globals) --------
__device__ __align__(16) __half g_xh  [(size_t)Mrows * Cc];
__device__ __align__(16) __half g_qkv [(size_t)Mrows * QKVW];
__device__ __align__(16) __half g_yh  [(size_t)Mrows * Cc];
__device__ __align__(16) __half g_wqkvt[(size_t)QKVW * Cc];
__device__ __align__(16) __half g_wot [(size_t)Cc * Cc];

__device__ __forceinline__ float ex2(float x) {
    float y; asm("ex2.approx.f32 %0, %1;" : "=f"(y) : "f"(x)); return y;
}
__device__ __forceinline__ uint32_t smem_to_u32(const void* p) {
    uint32_t a;
    asm("{ .reg .u64 t; cvta.to.shared.u64 t, %1; cvt.u32.u64 %0, t; }"
        : "=r"(a) : "l"(p));
    return a;
}
__device__ __forceinline__ uint32_t pack_h2(float lo, float hi) {
    __half2 h = __floats2half2_rn(lo, hi);
    return *(uint32_t*)&h;
}
__device__ __forceinline__ void mma_f16(float* c, const uint32_t* a, const uint32_t* b) {
    asm volatile(
        "mma.sync.aligned.m16n8k16.row.col.f32.f16.f16.f32 "
        "{%0,%1,%2,%3}, {%4,%5,%6,%7}, {%8,%9}, {%0,%1,%2,%3};"
        : "+f"(c[0]), "+f"(c[1]), "+f"(c[2]), "+f"(c[3])
        : "r"(a[0]), "r"(a[1]), "r"(a[2]), "r"(a[3]), "r"(b[0]), "r"(b[1]));
}
#define LDMATRIX_X4(r0, r1, r2, r3, addr) \
    asm volatile("ldmatrix.sync.aligned.m8n8.x4.shared.b16 {%0,%1,%2,%3}, [%4];" \
        : "=r"(r0), "=r"(r1), "=r"(r2), "=r"(r3) : "r"(addr))
#define LDMATRIX_X4_TRANS(r0, r1, r2, r3, addr) \
    asm volatile("ldmatrix.sync.aligned.m8n8.x4.trans.shared.b16 {%0,%1,%2,%3}, [%4];" \
        : "=r"(r0), "=r"(r1), "=r"(r2), "=r"(r3) : "r"(addr))
#define CP_ASYNC16(sm, gp) \
    asm volatile("cp.async.cg.shared.global [%0], [%1], 16;" :: "r"(sm), "l"(gp))
#define CP_COMMIT asm volatile("cp.async.commit_group;" ::: "memory")
#define CP_WAIT2  asm volatile("cp.async.wait_group 2;"  ::: "memory")
#define CP_WAIT1  asm volatile("cp.async.wait_group 1;"  ::: "memory")

// =================== fp16 mma GEMM ==========================================
// C[M,N] = A[M,K] @ Bt[N,K]^T. CTA 128x128, 4 warps @ 64x64,
// K-chunk 32 halves, 4-stage cp.async (wait_group 2), 2 CTAs/SM.
#define KCG 32                          // K-chunk (halves)
#define KPG 40                          // smem row stride (halves)
#define GA_H (128*KPG)                  // halves per A stage
#define STG_H (2*GA_H)                  // A + B
#define NSTG 4
#define GEMM_SMEM (NSTG * STG_H * 2)    // 81920 B -> 2 CTAs/SM

__global__ __launch_bounds__(128, 2) void gemm_hmma(
    const __half* __restrict__ A, const __half* __restrict__ Bt,
    float* __restrict__ Cf, __half* __restrict__ Ch,
    int M, int N, int K, int out_half)
{
    extern __shared__ __half smg[];
    const uint32_t smb = smem_to_u32(smg);
    const int tid = threadIdx.x, wid = tid >> 5, lane = tid & 31;
    const int lr = lane >> 2, lc = lane & 3;
    const int wm = (wid & 1) * 64;
    const int wn = (wid >> 1) * 64;
    const int bm = blockIdx.y * 128;
    const int bn = blockIdx.x * 128;
    const int nc = K / KCG;

    const int a_row = lane & 15, a_k = (lane >> 4) * 8;
    const int b_row = (lane & 7) + ((lane >> 4) << 3), b_k = lane & 8;

    float acc[4][8][4];
#pragma unroll
    for (int i = 0; i < 4; i++)
#pragma unroll
        for (int j = 0; j < 8; j++)
#pragma unroll
            for (int r = 0; r < 4; r++) acc[i][j][r] = 0.f;

#define GISSUE(chunk) do {                                                      \
        const uint32_t bse = smb + (uint32_t)((chunk) & 3) * (STG_H * 2);       \
        const int kb = (chunk) * KCG;                                           \
        _Pragma("unroll")                                                       \
        for (int n = 0; n < 4; n++) {                                           \
            int i = tid + n * 128, r = i >> 2, cc = (i & 3) * 8;                \
            CP_ASYNC16(bse + (uint32_t)(r * KPG + cc) * 2u,                     \
                       A + (size_t)(bm + r) * K + kb + cc);                     \
            CP_ASYNC16(bse + (uint32_t)(GA_H * 2) + (uint32_t)(r * KPG + cc) * 2u, \
                       Bt + (size_t)(bn + r) * K + kb + cc);                    \
        }                                                                       \
    } while (0)

    GISSUE(0); CP_COMMIT;
    GISSUE(1); CP_COMMIT;
    GISSUE(2); CP_COMMIT;

    for (int c = 0; c < nc; c++) {
        CP_WAIT2;
        __syncthreads();
        if (c + 3 < nc) GISSUE(c + 3);
        CP_COMMIT;

        const uint32_t sA = smb + (uint32_t)(c & 3) * (STG_H * 2);
        const uint32_t sB = sA + GA_H * 2;
#pragma unroll
        for (int ks = 0; ks < 2; ks++) {
            const int k0 = ks * 16;
            uint32_t af[4][4], bf[8][2];
#pragma unroll
            for (int mf = 0; mf < 4; mf++) {
                const uint32_t ad = sA +
                    (uint32_t)((wm + mf*16 + a_row) * KPG + k0 + a_k) * 2u;
                LDMATRIX_X4(af[mf][0], af[mf][1], af[mf][2], af[mf][3], ad);
            }
#pragma unroll
            for (int ng = 0; ng < 4; ng++) {
                const uint32_t ad = sB +
                    (uint32_t)((wn + ng*16 + b_row) * KPG + k0 + b_k) * 2u;
                uint32_t r0, r1, r2, r3;
                LDMATRIX_X4(r0, r1, r2, r3, ad);
                bf[2*ng][0] = r0;   bf[2*ng][1] = r1;
                bf[2*ng+1][0] = r2; bf[2*ng+1][1] = r3;
            }
#pragma unroll
            for (int mf = 0; mf < 4; mf++)
#pragma unroll
                for (int nf = 0; nf < 8; nf++)
                    mma_f16(acc[mf][nf], af[mf], bf[nf]);
        }
    }

#pragma unroll
    for (int mf = 0; mf < 4; mf++) {
#pragma unroll
        for (int nf = 0; nf < 8; nf++) {
            const int row = bm + wm + mf * 16 + lr;
            const int col = bn + wn + nf * 8 + lc * 2;
            if (out_half) {
                *(uint32_t*)(Ch + (size_t)row * N + col) =
                    pack_h2(acc[mf][nf][0], acc[mf][nf][1]);
                *(uint32_t*)(Ch + (size_t)(row + 8) * N + col) =
                    pack_h2(acc[mf][nf][2], acc[mf][nf][3]);
            } else {
                *(float2*)(Cf + (size_t)row * N + col) =
                    make_float2(acc[mf][nf][0], acc[mf][nf][1]);
                *(float2*)(Cf + (size_t)(row + 8) * N + col) =
                    make_float2(acc[mf][nf][2], acc[mf][nf][3]);
            }
        }
    }
#undef GISSUE
}

// =================== fused prep kernel ======================================
#define PREP_GRID 11264

__global__ __launch_bounds__(256) void prep(
    const float* __restrict__ x,
    const float* __restrict__ Wq, const float* __restrict__ Wk,
    const float* __restrict__ Wv, const float* __restrict__ Wo)
{
    const int bid = blockIdx.x, tid = threadIdx.x;
    if (bid < 9216) {
        __shared__ float t[32][33];
        const float* in; __half* out; int K, N, bx, by;
        if (bid < 4096)      { in = Wq; out = g_wqkvt;                     K = Cc; N = Cc;  bx = bid & 63;        by = bid >> 6; }
        else if (bid < 4608) { in = Wk; out = g_wqkvt + (size_t)2048 * Cc; K = Cc; N = 256; bx = (bid-4096) & 7;  by = (bid-4096) >> 3; }
        else if (bid < 5120) { in = Wv; out = g_wqkvt + (size_t)2304 * Cc; K = Cc; N = 256; bx = (bid-4608) & 7;  by = (bid-4608) >> 3; }
        else                 { in = Wo; out = g_wot;                       K = Cc; N = Cc;  bx = (bid-5120) & 63; by = (bid-5120) >> 6; }
        const int xx = tid & 31, yy = tid >> 5;
        const int n0 = bx * 32, k0 = by * 32;
        for (int i = yy; i < 32; i += 8)
            t[i][xx] = in[(size_t)(k0 + i) * N + n0 + xx];
        __syncthreads();
        for (int i = yy; i < 32; i += 8)
            out[(size_t)(n0 + i) * K + k0 + xx] = __float2half_rn(t[xx][i]);
    } else {
        const int n4 = Mrows * Cc / 4;
        const float4* in = (const float4*)x;
        __half2* out = (__half2*)g_xh;
        for (int i = (bid - 9216) * 256 + tid; i < n4; i += 2048 * 256) {
            float4 v = in[i];
            out[2*i]   = __floats2half2_rn(v.x, v.y);
            out[2*i+1] = __floats2half2_rn(v.z, v.w);
        }
    }
}

// =================== fp16 mma flash attention ===============================
// BQ=64 (4 warps x 16 rows), BK=128, 128 threads, 2 CTAs/SM.
// 3-buffer smem: K double-buffered, V single-buffered (issued one iter ahead).
// grid (NH*Bc, Tc/BQ): globally heavy-first (y=0 -> heaviest qt).
#define BQ 64
#define BK 128
#define KPH 136
#define KTILE (BK * KPH * 2)              // 34816 B
#define ATT_SMEM (3 * KTILE)              // 104448 B -> 2 CTAs/SM

__global__ __launch_bounds__(128, 2) void attn_hmma()
{
    extern __shared__ __half smh[];
    const uint32_t smb = smem_to_u32(smh);
    const int tid = threadIdx.x, wid = tid >> 5, lane = tid & 31;
    const int lr = lane >> 2, lc = lane & 3;
    const int qt = (int)(gridDim.y - 1 - blockIdx.y);   // globally heavy-first
    const int h = blockIdx.x & (NH - 1), b = blockIdx.x >> 4, g = h >> 3;
    const int q0 = qt * BQ, m0 = wid * 16;

    const uint32_t offK0 = 0, offK1 = KTILE, offV = 2*KTILE;

    const int b_row = (lane & 7) + ((lane >> 4) << 3), b_k = lane & 8;

    uint32_t qf[8][4];
    {
        const __half* q0p = g_qkv + ((size_t)(b*Tc + q0 + m0 + lr))*QKVW + h*DH;
        const __half* q8p = q0p + (size_t)8*QKVW;
#pragma unroll
        for (int ks = 0; ks < 8; ks++) {
            qf[ks][0] = *(const uint32_t*)(q0p + ks*16 + 2*lc);
            qf[ks][1] = *(const uint32_t*)(q8p + ks*16 + 2*lc);
            qf[ks][2] = *(const uint32_t*)(q0p + ks*16 + 2*lc + 8);
            qf[ks][3] = *(const uint32_t*)(q8p + ks*16 + 2*lc + 8);
        }
    }

    float of[16][4];
#pragma unroll
    for (int i = 0; i < 16; i++)
#pragma unroll
        for (int r = 0; r < 4; r++) of[i][r] = 0.f;
    float mrow0 = -1e30f, mrow1 = -1e30f, lrow0 = 0.f, lrow1 = 0.f;
    const float cs = 0.12752191711633058f;   // log2(e)/sqrt(128)

    const __half* gK = g_qkv + (size_t)(b*Tc)*QKVW + 2048 + g*DH;
    const __half* gV = gK + 256;
    const int nb = qt / 2 + 1;     // #128-key blocks covering keys <= q0+63

#define AFILL(dst, src) do {                                                  \
        _Pragma("unroll")                                                     \
        for (int n = 0; n < 16; n++) {                                        \
            int i = tid + n*128;                                              \
            int r = i >> 4, c = (i & 15) * 8;                                 \
            CP_ASYNC16((dst) + (uint32_t)(r*KPH + c)*2u,                      \
                       (src) + (size_t)r*QKVW + c);                           \
        }                                                                     \
    } while (0)

    // prologue: K0, V0, K1 (empty-commit if absent)
    AFILL(smb + offK0, gK); CP_COMMIT;
    AFILL(smb + offV,  gV); CP_COMMIT;
    if (nb > 1) AFILL(smb + offK1, gK + (size_t)BK*QKVW);
    CP_COMMIT;

    for (int jt = 0; jt < nb; jt++) {
        CP_WAIT1;              // K_jt and V_jt landed; K_{jt+1} may fly
        __syncthreads();

        const uint32_t Kb = smb + ((jt & 1) ? offK1 : offK0);
        const uint32_t Vb = smb + offV;
        const int k0 = jt * BK;

        // ---- S = Q @ K^T (16 x 128 per warp)
        float sf[16][4];
#pragma unroll
        for (int nf = 0; nf < 16; nf++)
#pragma unroll
            for (int r = 0; r < 4; r++) sf[nf][r] = 0.f;

#pragma unroll
        for (int ks = 0; ks < 8; ks++) {
            uint32_t bf[16][2];
#pragma unroll
            for (int ng = 0; ng < 8; ng++) {
                const uint32_t ad = Kb +
                    (uint32_t)((ng*16 + b_row) * KPH + ks*16 + b_k) * 2u;
                uint32_t r0, r1, r2, r3;
                LDMATRIX_X4(r0, r1, r2, r3, ad);
                bf[2*ng][0] = r0;   bf[2*ng][1] = r1;
                bf[2*ng+1][0] = r2; bf[2*ng+1][1] = r3;
            }
#pragma unroll
            for (int nf = 0; nf < 16; nf++)
                mma_f16(sf[nf], qf[ks], bf[nf]);
        }

#pragma unroll
        for (int nf = 0; nf < 16; nf++) {
            sf[nf][0] *= cs; sf[nf][1] *= cs; sf[nf][2] *= cs; sf[nf][3] *= cs;
        }
        if (jt == nb - 1) {    // only last block can cross the diagonal
            const int row0 = q0 + m0 + lr, row1 = row0 + 8;
#pragma unroll
            for (int nf = 0; nf < 16; nf++) {
                const int col = k0 + nf*8 + lc*2;
                if (col     > row0) sf[nf][0] = -1e30f;
                if (col + 1 > row0) sf[nf][1] = -1e30f;
                if (col     > row1) sf[nf][2] = -1e30f;
                if (col + 1 > row1) sf[nf][3] = -1e30f;
            }
        }

        // ---- online softmax (log2 domain)
        float mx0 = mrow0, mx1 = mrow1;
#pragma unroll
        for (int nf = 0; nf < 16; nf++) {
            mx0 = fmaxf(mx0, fmaxf(sf[nf][0], sf[nf][1]));
            mx1 = fmaxf(mx1, fmaxf(sf[nf][2], sf[nf][3]));
        }
        mx0 = fmaxf(mx0, __shfl_xor_sync(0xffffffffu, mx0, 1, 4));
        mx0 = fmaxf(mx0, __shfl_xor_sync(0xffffffffu, mx0, 2, 4));
        mx1 = fmaxf(mx1, __shfl_xor_sync(0xffffffffu, mx1, 1, 4));
        mx1 = fmaxf(mx1, __shfl_xor_sync(0xffffffffu, mx1, 2, 4));
        const float alpha0 = ex2(mrow0 - mx0);
        const float alpha1 = ex2(mrow1 - mx1);
        mrow0 = mx0; mrow1 = mx1;

        float s0 = 0.f, s1 = 0.f;
#pragma unroll
        for (int nf = 0; nf < 16; nf++) {
            sf[nf][0] = ex2(sf[nf][0] - mx0);
            sf[nf][1] = ex2(sf[nf][1] - mx0);
            sf[nf][2] = ex2(sf[nf][2] - mx1);
            sf[nf][3] = ex2(sf[nf][3] - mx1);
            s0 += sf[nf][0] + sf[nf][1];
            s1 += sf[nf][2] + sf[nf][3];
        }
        s0 += __shfl_xor_sync(0xffffffffu, s0, 1, 4);
        s0 += __shfl_xor_sync(0xffffffffu, s0, 2, 4);
        s1 += __shfl_xor_sync(0xffffffffu, s1, 1, 4);
        s1 += __shfl_xor_sync(0xffffffffu, s1, 2, 4);
        lrow0 = lrow0 * alpha0 + s0;
        lrow1 = lrow1 * alpha1 + s1;

#pragma unroll
        for (int nf2 = 0; nf2 < 16; nf2++) {
            of[nf2][0] *= alpha0; of[nf2][1] *= alpha0;
            of[nf2][2] *= alpha1; of[nf2][3] *= alpha1;
        }

        // ---- O += P @ V (P in-register, V via ldmatrix.trans)
#pragma unroll
        for (int ks2 = 0; ks2 < 8; ks2++) {
            uint32_t pf[4];
            pf[0] = pack_h2(sf[2*ks2][0],   sf[2*ks2][1]);
            pf[1] = pack_h2(sf[2*ks2][2],   sf[2*ks2][3]);
            pf[2] = pack_h2(sf[2*ks2+1][0], sf[2*ks2+1][1]);
            pf[3] = pack_h2(sf[2*ks2+1][2], sf[2*ks2+1][3]);
            const uint32_t vrow = (uint32_t)(ks2*16 + (lane & 15));
#pragma unroll
            for (int np = 0; np < 8; np++) {
                const uint32_t vaddr = Vb +
                    (vrow * KPH + (uint32_t)(np*16 + (lane >> 4) * 8)) * 2u;
                uint32_t v0, v1, v2, v3;
                LDMATRIX_X4_TRANS(v0, v1, v2, v3, vaddr);
                uint32_t vf0[2] = {v0, v1}, vf1[2] = {v2, v3};
                mma_f16(of[2*np],   pf, vf0);
                mma_f16(of[2*np+1], pf, vf1);
            }
        }
        __syncthreads();   // PV done -> V buffer may be overwritten

        // issue next-iteration V (and K two ahead)
        if (jt + 1 < nb) {
            AFILL(smb + offV, gV + (size_t)(jt+1)*BK*QKVW); CP_COMMIT;
            if (jt + 2 < nb)
                AFILL(smb + (((jt+2) & 1) ? offK1 : offK0),
                      gK + (size_t)(jt+2)*BK*QKVW);
            CP_COMMIT;
        }
    }
#undef AFILL

    const float inv0 = 1.f / lrow0, inv1 = 1.f / lrow1;
    const int row0 = q0 + m0 + lr, row1 = row0 + 8;
#pragma unroll
    for (int nf2 = 0; nf2 < 16; nf2++) {
        const int col = h*DH + nf2*8 + lc*2;
        *(uint32_t*)(g_yh + (size_t)(b*Tc + row0)*Cc + col) =
            pack_h2(of[nf2][0]*inv0, of[nf2][1]*inv0);
        *(uint32_t*)(g_yh + (size_t)(b*Tc + row1)*Cc + col) =
            pack_h2(of[nf2][2]*inv1, of[nf2][3]*inv1);
    }
}

// =================== host side ==============================================
extern "C" void kernel_launch(void* const* d_in, const int* in_sizes, int n_in,
                              void* d_out, int out_size)
{
    const float* x  = (const float*)d_in[0];
    const float* Wq = (const float*)d_in[1];
    const float* Wk = (const float*)d_in[2];
    const float* Wv = (const float*)d_in[3];
    const float* Wo = (const float*)d_in[4];
    float* out = (float*)d_out;

    static bool inited = false;
    static __half *xh, *qkvp, *yh, *wqkvt, *wot;
    if (!inited) {
        cudaGetSymbolAddress((void**)&xh,    g_xh);
        cudaGetSymbolAddress((void**)&qkvp,  g_qkv);
        cudaGetSymbolAddress((void**)&yh,    g_yh);
        cudaGetSymbolAddress((void**)&wqkvt, g_wqkvt);
        cudaGetSymbolAddress((void**)&wot,   g_wot);
        cudaFuncSetAttribute(attn_hmma, cudaFuncAttributeMaxDynamicSharedMemorySize,
                             ATT_SMEM);
        cudaFuncSetAttribute(gemm_hmma, cudaFuncAttributeMaxDynamicSharedMemorySize,
                             GEMM_SMEM);
        inited = true;
    }

    prep<<<PREP_GRID, 256>>>(x, Wq, Wk, Wv, Wo);

    gemm_hmma<<<dim3(QKVW / 128, Mrows / 128), 128, GEMM_SMEM>>>(
        xh, wqkvt, nullptr, qkvp, Mrows, QKVW, Cc, 1);
    attn_hmma<<<dim3(NH * Bc, Tc / BQ), 128, ATT_SMEM>>>();
    gemm_hmma<<<dim3(Cc / 128, Mrows / 128), 128, GEMM_SMEM>>>(
        yh, wot, out, nullptr, Mrows, Cc, Cc, 0);
}